// round 12
// baseline (speedup 1.0000x reference)
#include <cuda_runtime.h>
#include <cuda_bf16.h>
#include <cuda_fp16.h>
#include <cstdint>

// GATv2 with algebraic reductions:
//   attn[e,h] = exp(ql[src]) / sum_{s in N(dst)} exp(ql[s])   (kl cancels -> Wk/bk unused)
//   out[d] = relu( sum_{s in N(d)} P[s] / sum_{s in N(d)} w[s] ),
//   P = q * exp(ql) (fp16), w = exp(ql) (fp32), node-level (GEMM epilogue).
// 4 kernels: [hist] -> [scan(+re-zero cnt)] -> [gemm(in-block W build)|scatter] -> [gather].
// Invariant: g_cnt all-zero at entry (zero-init at load; scan re-zeroes each call).

#define MAXN 50000
#define MAXE 600000

__device__ __half  g_P   [MAXN * 128];   // q * exp(ql), fp16
__device__ float   g_w   [MAXN * 8];     // exp(ql)
__device__ int     g_cnt [MAXN + 4];     // ALWAYS zero between launches
__device__ int     g_roff[MAXN + 4];
__device__ int     g_cur [MAXN + 4];
__device__ int     g_csr [MAXE];

// ---------------------------------------------------------------------------
// K0: histogram of dst degrees, 1 edge/thread (max MLP via thread count)
// ---------------------------------------------------------------------------
__global__ void hist_kernel(const int* __restrict__ dst, int E)
{
    int e = blockIdx.x * blockDim.x + threadIdx.x;
    if (e < E) atomicAdd(&g_cnt[dst[e]], 1);
}

// ---------------------------------------------------------------------------
// K1: vectorized exclusive scan -> g_roff + g_cur, re-zero g_cnt (invariant).
// ---------------------------------------------------------------------------
__global__ void scan_kernel(int n)
{
    __shared__ int sh[1024];
    int tid = threadIdx.x;
    int per = ((n + 1023) / 1024 + 3) & ~3;
    int beg = tid * per; if (beg > n) beg = n;
    int end = beg + per; if (end > n) end = n;

    int s = 0;
    int i = beg;
    for (; i + 4 <= end; i += 4) {
        int4 v = *(const int4*)&g_cnt[i];
        s += v.x + v.y + v.z + v.w;
    }
    for (; i < end; i++) s += g_cnt[i];
    sh[tid] = s;
    __syncthreads();
#pragma unroll
    for (int off = 1; off < 1024; off <<= 1) {
        int v = (tid >= off) ? sh[tid - off] : 0;
        __syncthreads();
        sh[tid] += v;
        __syncthreads();
    }
    int run = (tid > 0) ? sh[tid - 1] : 0;
    const int4 z4 = make_int4(0, 0, 0, 0);
    i = beg;
    for (; i + 4 <= end; i += 4) {
        int4 v = *(const int4*)&g_cnt[i];
        int4 p;
        p.x = run;
        p.y = p.x + v.x;
        p.z = p.y + v.y;
        p.w = p.z + v.z;
        run = p.w + v.w;
        *(int4*)&g_roff[i] = p;
        *(int4*)&g_cur[i]  = p;
        *(int4*)&g_cnt[i]  = z4;       // restore invariant
    }
    for (; i < end; i++) {
        g_roff[i] = run;
        g_cur[i]  = run;
        run += g_cnt[i];
        g_cnt[i] = 0;
    }
    if (tid == 1023) g_roff[n] = sh[1023];
}

// ---------------------------------------------------------------------------
// K2: fused [gemm | scatter] by blockIdx.
//     GEMM blocks build their own bf16 hi/lo weight tiles in smem from
//     Wq/bq/attn_w (no separate build kernel, no global weight round-trip).
// ---------------------------------------------------------------------------
#define B_STRIDE 272
#define SMB_HI   0
#define SMB_LO   (136 * B_STRIDE)
#define SMB_BF   (2 * 136 * B_STRIDE)           // fp32 bias [136]
#define SMB_TOT  (2 * 136 * B_STRIDE + 544)     // 74528 bytes

__device__ __forceinline__ void mma_bf16(float* c, const uint32_t* a,
                                         uint32_t b0, uint32_t b1) {
    asm volatile(
        "mma.sync.aligned.m16n8k16.row.col.f32.bf16.bf16.f32 "
        "{%0,%1,%2,%3}, {%4,%5,%6,%7}, {%8,%9}, {%0,%1,%2,%3};"
        : "+f"(c[0]), "+f"(c[1]), "+f"(c[2]), "+f"(c[3])
        : "r"(a[0]), "r"(a[1]), "r"(a[2]), "r"(a[3]), "r"(b0), "r"(b1));
}

__device__ __forceinline__ void cvt2(float2 f, uint32_t& hi, uint32_t& lo) {
    __nv_bfloat16 h0 = __float2bfloat16(f.x);
    __nv_bfloat16 h1 = __float2bfloat16(f.y);
    __nv_bfloat16 l0 = __float2bfloat16(f.x - __bfloat162float(h0));
    __nv_bfloat16 l1 = __float2bfloat16(f.y - __bfloat162float(h1));
    __nv_bfloat162 H(h0, h1), L(l0, l1);
    hi = *(uint32_t*)&H;
    lo = *(uint32_t*)&L;
}

__device__ __forceinline__ void split_store(char* bhi, char* blo, int c, int k, float v) {
    __nv_bfloat16 hi = __float2bfloat16(v);
    __nv_bfloat16 lo = __float2bfloat16(v - __bfloat162float(hi));
    *(__nv_bfloat16*)(bhi + c * B_STRIDE + k * 2) = hi;
    *(__nv_bfloat16*)(blo + c * B_STRIDE + k * 2) = lo;
}

__global__ void __launch_bounds__(256) gemm_scatter_kernel(
    const float* __restrict__ x, const float* __restrict__ Wq,
    const float* __restrict__ bq, const float* __restrict__ aw,
    const int* __restrict__ src, const int* __restrict__ dst,
    int n, int E, int gemmBlocks)
{
    extern __shared__ char smem[];
    int tid = threadIdx.x;

    if ((int)blockIdx.x >= gemmBlocks) {
        // ---------------- scatter part ----------------
        int b = blockIdx.x - gemmBlocks;
        int t = b * 256 + tid;
        int T = (gridDim.x - gemmBlocks) * 256;
#pragma unroll
        for (int j = 0; j < 4; j++) {
            int e = t + j * T;
            if (e < E) {
                int pos = atomicAdd(&g_cur[dst[e]], 1);
                g_csr[pos] = src[e];
            }
        }
        return;
    }

    // ---------------- gemm part ----------------
    char*  bhi = smem + SMB_HI;
    char*  blo = smem + SMB_LO;
    float* sbf = (float*)(smem + SMB_BF);

    // build B in-block: cols 0..127 = Wq^T (k-major rows), cols 128..135 = wql
    for (int e = tid; e < 128 * 128; e += 256) {
        int r = e >> 7, c = e & 127;          // r = k index; coalesced Wq read
        split_store(bhi, blo, c, r, Wq[e]);
    }
    for (int e = tid; e < 128 * 8; e += 256) {
        int r = e >> 3, h = e & 7;
        float s = 0.f;
#pragma unroll
        for (int d = 0; d < 16; d++) s += Wq[r * 128 + h * 16 + d] * aw[d * 8 + h];
        split_store(bhi, blo, 128 + h, r, s);
    }
    if (tid < 136) {
        float v;
        if (tid < 128) {
            v = bq[tid];
        } else {
            int h = tid - 128;
            float s = 0.f;
#pragma unroll
            for (int d = 0; d < 16; d++) s += bq[h * 16 + d] * aw[d * 8 + h];
            v = s;
        }
        sbf[tid] = v;
    }
    __syncthreads();

    int w    = tid >> 5;
    int lane = tid & 31;
    int g    = lane >> 2;
    int t    = lane & 3;
    int rb   = blockIdx.x * 128 + w * 16;
    int r0   = rb + g;
    int r1   = r0 + 8;
    int rc0  = (r0 < n) ? r0 : (n - 1);
    int rc1  = (r1 < n) ? r1 : (n - 1);
    const float* xr0 = &x[(size_t)rc0 * 128];
    const float* xr1 = &x[(size_t)rc1 * 128];

    float C[17][4];
#pragma unroll
    for (int j = 0; j < 17; j++)
#pragma unroll
        for (int q = 0; q < 4; q++) C[j][q] = 0.f;

    for (int k0 = 0; k0 < 128; k0 += 16) {
        float2 f00 = *(const float2*)&xr0[k0 + 2 * t];
        float2 f10 = *(const float2*)&xr1[k0 + 2 * t];
        float2 f01 = *(const float2*)&xr0[k0 + 2 * t + 8];
        float2 f11 = *(const float2*)&xr1[k0 + 2 * t + 8];
        uint32_t ah[4], al[4];
        cvt2(f00, ah[0], al[0]);
        cvt2(f10, ah[1], al[1]);
        cvt2(f01, ah[2], al[2]);
        cvt2(f11, ah[3], al[3]);

        const char* bh = bhi + k0 * 2 + t * 4;
        const char* bl = blo + k0 * 2 + t * 4;
#pragma unroll
        for (int j = 0; j < 17; j++) {
            int brow = (j * 8 + g) * B_STRIDE;
            uint32_t bh0 = *(const uint32_t*)(bh + brow);
            uint32_t bh1 = *(const uint32_t*)(bh + brow + 16);
            uint32_t bl0 = *(const uint32_t*)(bl + brow);
            uint32_t bl1 = *(const uint32_t*)(bl + brow + 16);
            mma_bf16(C[j], ah, bh0, bh1);
            mma_bf16(C[j], al, bh0, bh1);
            mma_bf16(C[j], ah, bl0, bl1);
        }
    }

    // epilogue: e = exp(ql + bias); quad-broadcast; write P (fp16) and w (fp32)
    bool v0 = (r0 < n), v1 = (r1 < n);
    float bql0 = sbf[128 + 2 * t], bql1 = sbf[128 + 2 * t + 1];
    float ex00 = __expf(C[16][0] + bql0);
    float ex01 = __expf(C[16][1] + bql1);
    float ex10 = __expf(C[16][2] + bql0);
    float ex11 = __expf(C[16][3] + bql1);

    float e0[8], e1[8];
#pragma unroll
    for (int tt = 0; tt < 4; tt++) {
        int sl = (lane & ~3) | tt;
        e0[2 * tt]     = __shfl_sync(0xffffffffu, ex00, sl);
        e0[2 * tt + 1] = __shfl_sync(0xffffffffu, ex01, sl);
        e1[2 * tt]     = __shfl_sync(0xffffffffu, ex10, sl);
        e1[2 * tt + 1] = __shfl_sync(0xffffffffu, ex11, sl);
    }
    if (v0) {
        g_w[(size_t)r0 * 8 + 2 * t]     = ex00;
        g_w[(size_t)r0 * 8 + 2 * t + 1] = ex01;
    }
    if (v1) {
        g_w[(size_t)r1 * 8 + 2 * t]     = ex10;
        g_w[(size_t)r1 * 8 + 2 * t + 1] = ex11;
    }
#pragma unroll
    for (int j = 0; j < 16; j++) {
        int c = j * 8 + 2 * t;
        int h = j >> 1;
        float2 bias = *(const float2*)&sbf[c];
        if (v0) {
            float2 p = make_float2((C[j][0] + bias.x) * e0[h], (C[j][1] + bias.y) * e0[h]);
            *(__half2*)&g_P[(size_t)r0 * 128 + c] = __float22half2_rn(p);
        }
        if (v1) {
            float2 p = make_float2((C[j][2] + bias.x) * e1[h], (C[j][3] + bias.y) * e1[h]);
            *(__half2*)&g_P[(size_t)r1 * 128 + c] = __float22half2_rn(p);
        }
    }
}

// ---------------------------------------------------------------------------
// K3: warp-per-node gather. Coalesced csr + shfl broadcast; 4-edge groups
//     pair-summed in fp16 (HADD2), folded to fp32 once per group.
// ---------------------------------------------------------------------------
__global__ void __launch_bounds__(256) gather_kernel(float* __restrict__ out, int n)
{
    int warp = (blockIdx.x * blockDim.x + threadIdx.x) >> 5;
    int lane = threadIdx.x & 31;
    if (warp >= n) return;

    int beg = g_roff[warp];
    int deg = g_roff[warp + 1] - beg;
    int h   = lane >> 2;

    float4 acc = make_float4(0.f, 0.f, 0.f, 0.f);
    float den = 0.f;

    int i = 0;
    while (i < deg) {
        int cnt = min(32, deg - i);
        int sv = (lane < cnt) ? g_csr[beg + i + lane] : 0;
        int j = 0;
        for (; j + 4 <= cnt; j += 4) {
            int s0 = __shfl_sync(0xffffffffu, sv, j);
            int s1 = __shfl_sync(0xffffffffu, sv, j + 1);
            int s2 = __shfl_sync(0xffffffffu, sv, j + 2);
            int s3 = __shfl_sync(0xffffffffu, sv, j + 3);
            uint2 r0 = *(const uint2*)&g_P[(size_t)s0 * 128 + lane * 4];
            uint2 r1 = *(const uint2*)&g_P[(size_t)s1 * 128 + lane * 4];
            uint2 r2 = *(const uint2*)&g_P[(size_t)s2 * 128 + lane * 4];
            uint2 r3 = *(const uint2*)&g_P[(size_t)s3 * 128 + lane * 4];
            float w0 = g_w[(size_t)s0 * 8 + h];
            float w1 = g_w[(size_t)s1 * 8 + h];
            float w2 = g_w[(size_t)s2 * 8 + h];
            float w3 = g_w[(size_t)s3 * 8 + h];
            den += (w0 + w1) + (w2 + w3);
            // fp16 pairwise partial sums (group of 4), fold to fp32 once
            __half2 sx = __hadd2(__hadd2(*(__half2*)&r0.x, *(__half2*)&r1.x),
                                 __hadd2(*(__half2*)&r2.x, *(__half2*)&r3.x));
            __half2 sy = __hadd2(__hadd2(*(__half2*)&r0.y, *(__half2*)&r1.y),
                                 __hadd2(*(__half2*)&r2.y, *(__half2*)&r3.y));
            float2 fx = __half22float2(sx);
            float2 fy = __half22float2(sy);
            acc.x += fx.x; acc.y += fx.y; acc.z += fy.x; acc.w += fy.y;
        }
        for (; j < cnt; j++) {
            int s = __shfl_sync(0xffffffffu, sv, j);
            uint2 r = *(const uint2*)&g_P[(size_t)s * 128 + lane * 4];
            den += g_w[(size_t)s * 8 + h];
            float2 a = __half22float2(*(__half2*)&r.x);
            float2 b = __half22float2(*(__half2*)&r.y);
            acc.x += a.x; acc.y += a.y; acc.z += b.x; acc.w += b.y;
        }
        i += cnt;
    }

    float inv = (den > 0.f) ? __frcp_rn(den) : 0.f;
    float4 o;
    o.x = fmaxf(acc.x * inv, 0.f);
    o.y = fmaxf(acc.y * inv, 0.f);
    o.z = fmaxf(acc.z * inv, 0.f);
    o.w = fmaxf(acc.w * inv, 0.f);
    *(float4*)&out[(size_t)warp * 128 + lane * 4] = o;
}

// ---------------------------------------------------------------------------
extern "C" void kernel_launch(void* const* d_in, const int* in_sizes, int n_in,
                              void* d_out, int out_size)
{
    const float* x   = (const float*)d_in[0];
    const float* Wq  = (const float*)d_in[1];
    const float* bq  = (const float*)d_in[2];
    // d_in[3] (Wk), d_in[4] (bk): unused -- kl cancels in the per-dst softmax
    const float* aw  = (const float*)d_in[5];
    const int*   src = (const int*)d_in[6];
    const int*   dst = (const int*)d_in[7];
    float* out = (float*)d_out;

    int n = in_sizes[0] / 128;
    int E = in_sizes[6];
    if (n > MAXN) n = MAXN;
    if (E > MAXE) E = MAXE;

    cudaFuncSetAttribute(gemm_scatter_kernel,
                         cudaFuncAttributeMaxDynamicSharedMemorySize, SMB_TOT);

    int eq         = (E + 3) / 4;
    int gemmBlocks = (n + 127) / 128;       // 391
    int scatBlocks = (eq + 255) / 256;      // 586

    hist_kernel<<<(E + 255) / 256, 256>>>(dst, E);
    scan_kernel<<<1, 1024>>>(n);
    gemm_scatter_kernel<<<gemmBlocks + scatBlocks, 256, SMB_TOT>>>(
        x, Wq, bq, aw, src, dst, n, E, gemmBlocks);
    gather_kernel<<<((size_t)n * 32 + 255) / 256, 256>>>(out, n);
}